// round 14
// baseline (speedup 1.0000x reference)
#include <cuda_runtime.h>
#include <cuda_fp16.h>
#include <cstdint>
#include <math.h>

#define CIN   512
#define COUT  512
#define WDIM  512
#define NB    16
#define HW    64

#define CONV_COEF 0.014731391274719739f   /* 1/sqrt(9*512) */
#define FC_COEF   0.044194173824159216f   /* 1/sqrt(512)   */

#define NTILE 16384                        /* 16 imgs x 32x32 tiles */

/* ------------------------------------------------------------------ */
/* scratch (__device__ globals)                                        */
/* ------------------------------------------------------------------ */
__device__ __half g_V[(size_t)16 * 32 * 1024 * 256];
__device__ __half g_U[(size_t)16 * 512 * 512];
__device__ float  g_U32[(size_t)16 * 512 * 512];
__device__ __half g_M[(size_t)16 * NTILE * 512];
__device__ float  g_s[NB * CIN];
__device__ float  g_d[NB * COUT];
__device__ float  g_wsq[CIN * COUT];

__device__ __forceinline__ uint32_t su32(const void* p) {
    uint32_t a;
    asm("{ .reg .u64 t; cvta.to.shared.u64 t, %1; cvt.u32.u64 %0, t; }" : "=r"(a) : "l"(p));
    return a;
}
__device__ __forceinline__ void cp16(uint32_t dst, const void* src) {
    asm volatile("cp.async.cg.shared.global [%0], [%1], 16;" :: "r"(dst), "l"(src));
}
__device__ __forceinline__ void cp_commit() { asm volatile("cp.async.commit_group;" ::: "memory"); }
template <int N> __device__ __forceinline__ void cp_wait() {
    asm volatile("cp.async.wait_group %0;" :: "n"(N) : "memory");
}
__device__ __forceinline__ uint32_t h2u(__half2 h) { return *(uint32_t*)&h; }

__device__ __forceinline__ void mma16(float* c, uint32_t a0, uint32_t a1,
                                      uint32_t a2, uint32_t a3,
                                      uint32_t b0, uint32_t b1) {
    asm("mma.sync.aligned.m16n8k16.row.col.f32.f16.f16.f32 "
        "{%0,%1,%2,%3},{%4,%5,%6,%7},{%8,%9},{%0,%1,%2,%3};"
        : "+f"(c[0]), "+f"(c[1]), "+f"(c[2]), "+f"(c[3])
        : "r"(a0), "r"(a1), "r"(a2), "r"(a3), "r"(b0), "r"(b1));
}

/* ------------------------------------------------------------------ */
/* style: s[b][i] = dot(wl[b], fcw[:,i])*coef + fcb[i] + 1             */
/* grid (16, 4) x 128 thr, 4 accumulators (MLP 4)                      */
/* ------------------------------------------------------------------ */
__global__ void style_kernel(const float* __restrict__ wl,
                             const float* __restrict__ fcw,
                             const float* __restrict__ fcb) {
    __shared__ float swl[WDIM];
    const int b = blockIdx.x;
    const int i = blockIdx.y * 128 + threadIdx.x;
    for (int j = threadIdx.x; j < WDIM; j += 128)
        swl[j] = wl[b * WDIM + j];
    __syncthreads();
    float a0 = 0.f, a1 = 0.f, a2 = 0.f, a3 = 0.f;
#pragma unroll 4
    for (int j = 0; j < WDIM; j += 4) {
        a0 = fmaf(swl[j + 0], fcw[(size_t)(j + 0) * CIN + i], a0);
        a1 = fmaf(swl[j + 1], fcw[(size_t)(j + 1) * CIN + i], a1);
        a2 = fmaf(swl[j + 2], fcw[(size_t)(j + 2) * CIN + i], a2);
        a3 = fmaf(swl[j + 3], fcw[(size_t)(j + 3) * CIN + i], a3);
    }
    g_s[b * CIN + i] = ((a0 + a1) + (a2 + a3)) * FC_COEF + fcb[i] + 1.0f;
}

/* ------------------------------------------------------------------ */
/* demod: d[b][co] = rsqrt(sum_ci s^2 wsq * coef^2 + eps)              */
/* grid (16, 4) x 128 thr, 4 accumulators                              */
/* ------------------------------------------------------------------ */
__global__ void demod_kernel() {
    __shared__ float ss[CIN];
    const int b  = blockIdx.x;
    const int co = blockIdx.y * 128 + threadIdx.x;
    for (int ci = threadIdx.x; ci < CIN; ci += 128) {
        float s = g_s[b * CIN + ci];
        ss[ci] = s * s;
    }
    __syncthreads();
    float a0 = 0.f, a1 = 0.f, a2 = 0.f, a3 = 0.f;
#pragma unroll 4
    for (int ci = 0; ci < CIN; ci += 4) {
        a0 = fmaf(ss[ci + 0], g_wsq[(size_t)(ci + 0) * COUT + co], a0);
        a1 = fmaf(ss[ci + 1], g_wsq[(size_t)(ci + 1) * COUT + co], a1);
        a2 = fmaf(ss[ci + 2], g_wsq[(size_t)(ci + 2) * COUT + co], a2);
        a3 = fmaf(ss[ci + 3], g_wsq[(size_t)(ci + 3) * COUT + co], a3);
    }
    float acc = (a0 + a1) + (a2 + a3);
    g_d[b * COUT + co] = rsqrtf(acc * CONV_COEF * CONV_COEF + 1e-8f);
}

/* ------------------------------------------------------------------ */
/* U = G (w*coef) G^T  (fp32) + fused wsq = sum_tap w^2                */
/* ------------------------------------------------------------------ */
__global__ void u32_kernel(const float* __restrict__ w) {
    int idx = blockIdx.x * 256 + threadIdx.x;   /* 262144: (ci,co) */
    int co = idx & 511, ci = idx >> 9;
    float gm[3][3];
    float sq = 0.f;
#pragma unroll
    for (int tap = 0; tap < 9; tap++) {
        float v = w[(size_t)tap * CIN * COUT + ci * COUT + co];
        sq = fmaf(v, v, sq);
        gm[tap / 3][tap % 3] = v * CONV_COEF;
    }
    g_wsq[idx] = sq;
    float T[4][3];
#pragma unroll
    for (int c = 0; c < 3; c++) {
        T[0][c] = gm[0][c];
        T[1][c] = 0.5f * (gm[0][c] + gm[1][c] + gm[2][c]);
        T[2][c] = 0.5f * (gm[0][c] - gm[1][c] + gm[2][c]);
        T[3][c] = gm[2][c];
    }
#pragma unroll
    for (int r = 0; r < 4; r++) {
        float u0 = T[r][0];
        float u1 = 0.5f * (T[r][0] + T[r][1] + T[r][2]);
        float u2 = 0.5f * (T[r][0] - T[r][1] + T[r][2]);
        float u3 = T[r][2];
        g_U32[(((size_t)(r * 4 + 0)) * 512 + ci) * 512 + co] = u0;
        g_U32[(((size_t)(r * 4 + 1)) * 512 + ci) * 512 + co] = u1;
        g_U32[(((size_t)(r * 4 + 2)) * 512 + ci) * 512 + co] = u2;
        g_U32[(((size_t)(r * 4 + 3)) * 512 + ci) * 512 + co] = u3;
    }
}

/* pack U into m16n8k16 B-fragment order */
__global__ void upack_kernel() {
    int idx = blockIdx.x * 256 + threadIdx.x;   /* 524288 uint4 */
    int lane = idx & 31;
    int r = idx >> 5;
    int q  = r & 3;  r >>= 2;
    int wN = r & 1;  r >>= 1;
    int kg = r & 1;  r >>= 1;
    int ck = r & 15; r >>= 4;
    int nblk = r & 3;
    int pos  = r >> 2;
    int n  = nblk * 128 + wN * 64 + q * 16 + (lane >> 2);
    int k0 = ck * 32 + kg * 16 + 2 * (lane & 3);
    const float* up = g_U32 + (size_t)pos * 512 * 512;
    uint4 o;
    o.x = h2u(__floats2half2_rn(up[(size_t)k0 * 512 + n],       up[(size_t)(k0 + 1) * 512 + n]));
    o.y = h2u(__floats2half2_rn(up[(size_t)(k0 + 8) * 512 + n], up[(size_t)(k0 + 9) * 512 + n]));
    o.z = h2u(__floats2half2_rn(up[(size_t)k0 * 512 + n + 8],   up[(size_t)(k0 + 1) * 512 + n + 8]));
    o.w = h2u(__floats2half2_rn(up[(size_t)(k0 + 8) * 512 + n + 8], up[(size_t)(k0 + 9) * 512 + n + 8]));
    ((uint4*)g_U)[idx] = o;
}

/* ------------------------------------------------------------------ */
/* V = B^T (x*s) B — 2 tile-rows per block                             */
/* ------------------------------------------------------------------ */
__global__ void v_kernel(const float* __restrict__ x) {
    __shared__ float  sx[6 * 34 * 32];
    __shared__ __half sbuf[16 * 2 * 256];
    int idx = blockIdx.x;
    const int ckg = idx & 15;  idx >>= 4;
    const int h   = idx & 1;   idx >>= 1;
    const int typ = idx & 15;
    const int b   = idx >> 4;
    const int tid = threadIdx.x;

    const uint32_t sxa = su32(sx);
    {
        const int iyb = 4 * typ - 1, ixb = 32 * h - 1;
#pragma unroll
        for (int j = 0; j < 7; j++) {
            int i = tid + j * 256;
            if (i < 1632) {
                int q  = i & 7;
                int rc = i >> 3;
                int row = rc / 34, col = rc - 34 * row;
                int iy = iyb + row, ix = ixb + col;
                uint32_t dst = sxa + (rc * 32 + q * 4) * 4;
                if ((unsigned)iy < HW && (unsigned)ix < HW) {
                    cp16(dst, x + ((size_t)((b * HW + iy) * HW + ix)) * CIN + ckg * 32 + q * 4);
                } else {
                    *(float4*)((char*)sx + (rc * 32 + q * 4) * 4) = make_float4(0.f, 0.f, 0.f, 0.f);
                }
            }
        }
    }
    cp_commit();
    cp_wait<0>();
    __syncthreads();

#pragma unroll
    for (int p = 0; p < 2; p++) {
        if (p) __syncthreads();
#pragma unroll
        for (int u = 0; u < 2; u++) {
            int uid = tid + 256 * u;
            int tl = uid >> 5, ch = uid & 31;
            float s = g_s[b * 512 + ckg * 32 + ch];
            float d[4][4];
#pragma unroll
            for (int r = 0; r < 4; r++)
#pragma unroll
                for (int c = 0; c < 4; c++)
                    d[r][c] = sx[((2 * p + r) * 34 + 2 * tl + c) * 32 + ch] * s;
            float tt[4][4];
#pragma unroll
            for (int c = 0; c < 4; c++) {
                tt[0][c] = d[0][c] - d[2][c];
                tt[1][c] = d[1][c] + d[2][c];
                tt[2][c] = d[2][c] - d[1][c];
                tt[3][c] = d[1][c] - d[3][c];
            }
            int g = tl & 7, hh = tl >> 3;
            int kg = ch >> 4, kk = ch & 15, j = kk >> 1;
            int off = g * 64 + (j & 3) * 16 + (j >> 2) * 8 + hh * 4 + (kk & 1) * 2;
#pragma unroll
            for (int i = 0; i < 4; i++) {
                float v0 = tt[i][0] - tt[i][2];
                float v1 = tt[i][1] + tt[i][2];
                float v2 = tt[i][2] - tt[i][1];
                float v3 = tt[i][1] - tt[i][3];
                char* pl = (char*)sbuf + kg * 512;
                *(__half*)(pl + (i * 4 + 0) * 1024 + off) = __float2half(v0);
                *(__half*)(pl + (i * 4 + 1) * 1024 + off) = __float2half(v1);
                *(__half*)(pl + (i * 4 + 2) * 1024 + off) = __float2half(v2);
                *(__half*)(pl + (i * 4 + 3) * 1024 + off) = __float2half(v3);
            }
        }
        __syncthreads();
        const int mblk = b * 64 + (2 * typ + p) * 2 + h;
#pragma unroll
        for (int j = 0; j < 4; j++) {
            int cidx = tid + 256 * j;
            int plane = cidx >> 5, o16 = (cidx & 31) * 16;
            int pos = plane >> 1, kg = plane & 1;
            char* dst = (char*)g_V + (((size_t)(pos * 32 + ckg * 2 + kg)) * 1024 + mblk) * 512 + o16;
            *(uint4*)dst = *(uint4*)((char*)sbuf + plane * 512 + o16);
        }
    }
}

/* ------------------------------------------------------------------ */
/* GEMM per pos: M = V U ; CTA 128x128, warp 64x32, K-chunk 64         */
/* ------------------------------------------------------------------ */
#define GSTG 32768

__device__ __forceinline__ void g_load(uint32_t sb, const char* Vsrc, const char* Usrc,
                                       int s, int tid) {
#pragma unroll
    for (int j = 0; j < 8; j++) {
        int i = tid + 256 * j;
        if (i < 1024) {
            int kg = i >> 8, mo = i & 255;
            const char* src = Vsrc + ((size_t)(s * 4 + kg) * 1024 + (mo >> 5)) * 512 + (mo & 31) * 16;
            cp16(sb + kg * 4096 + mo * 16, src);
        } else {
            int i2 = i - 1024;
            cp16(sb + 16384 + i2 * 16, Usrc + (size_t)s * 16384 + i2 * 16);
        }
    }
}

__global__ __launch_bounds__(256, 2)
void gemm_kernel() {
    extern __shared__ char sm[];
    const int tid  = threadIdx.x;
    const int warp = tid >> 5;
    const int lane = tid & 31;
    const int g = lane >> 2, t = lane & 3;
    const int wn = warp & 3, wm = warp >> 2;
    const int nblk = blockIdx.x;
    const int mby  = blockIdx.y;
    const int pos  = blockIdx.z;

    const char* Vsrc = (const char*)g_V + ((size_t)pos * 32 * 1024 + (size_t)mby * 8) * 512;
    const char* Usrc = (const char*)g_U + (size_t)((pos * 4 + nblk) * 16) * 8192;
    const uint32_t sb = su32(sm);

    float acc[4][4][4];
#pragma unroll
    for (int mi = 0; mi < 4; mi++)
#pragma unroll
        for (int ni = 0; ni < 4; ni++)
#pragma unroll
            for (int r = 0; r < 4; r++) acc[mi][ni][r] = 0.f;

    g_load(sb, Vsrc, Usrc, 0, tid); cp_commit();
    g_load(sb + GSTG, Vsrc, Usrc, 1, tid); cp_commit();

    for (int s = 0; s < 8; s++) {
        cp_wait<1>();
        __syncthreads();
        const int s2 = s + 2;
        if (s2 < 8)
            g_load(sb + (s2 % 3) * GSTG, Vsrc, Usrc, s2, tid);
        cp_commit();

        const char* st = sm + (s % 3) * GSTG;
#pragma unroll
        for (int j = 0; j < 4; j++) {
            const char* ab = st + j * 4096 + wm * 2048 + g * 64 + t * 16;
            float4 Af[4];
#pragma unroll
            for (int mi = 0; mi < 4; mi++)
                Af[mi] = *(const float4*)(ab + mi * 512);
            const char* bb = st + 16384 + (j >> 1) * 8192 + (j & 1) * 4096
                           + (wn >> 1) * 2048 + (wn & 1) * 1024 + lane * 16;
            float4 Bf[2];
            Bf[0] = *(const float4*)bb;
            Bf[1] = *(const float4*)(bb + 512);
#pragma unroll
            for (int mi = 0; mi < 4; mi++)
#pragma unroll
                for (int ni = 0; ni < 4; ni++) {
                    const float4& B = Bf[ni >> 1];
                    uint32_t b0 = __float_as_uint((ni & 1) ? B.z : B.x);
                    uint32_t b1 = __float_as_uint((ni & 1) ? B.w : B.y);
                    mma16(acc[mi][ni],
                          __float_as_uint(Af[mi].x), __float_as_uint(Af[mi].y),
                          __float_as_uint(Af[mi].z), __float_as_uint(Af[mi].w),
                          b0, b1);
                }
        }
    }

    __half* Mp = g_M + (size_t)pos * NTILE * 512;
    const int m0 = mby * 128 + wm * 64;
    const int c0 = nblk * 128 + wn * 32;
#pragma unroll
    for (int mi = 0; mi < 4; mi++) {
        int r0 = m0 + mi * 16 + g;
#pragma unroll
        for (int ni = 0; ni < 4; ni++) {
            int cc = c0 + (ni >> 1) * 16 + (ni & 1) * 8 + t * 2;
            *(uint32_t*)(Mp + (size_t)r0 * 512 + cc) =
                h2u(__floats2half2_rn(acc[mi][ni][0], acc[mi][ni][1]));
            *(uint32_t*)(Mp + (size_t)(r0 + 8) * 512 + cc) =
                h2u(__floats2half2_rn(acc[mi][ni][2], acc[mi][ni][3]));
        }
    }
}

/* ------------------------------------------------------------------ */
/* inverse transform: y = A^T M A, * demod + bias — 2 co per thread    */
/* ------------------------------------------------------------------ */
__device__ __forceinline__ float2 f2add(float2 a, float2 b) {
    return make_float2(a.x + b.x, a.y + b.y);
}
__device__ __forceinline__ float2 f2sub(float2 a, float2 b) {
    return make_float2(a.x - b.x, a.y - b.y);
}

__global__ void inv_kernel(const float* __restrict__ bias, float* __restrict__ out) {
    int Wu = blockIdx.x * 16 + (threadIdx.x >> 5);
    int lane = threadIdx.x & 31;
    int tile = Wu >> 3, cog = Wu & 7;
    int co = cog * 64 + lane * 2;
    int b = tile >> 10, tl = tile & 1023, ty = tl >> 5, tx = tl & 31;

    float2 M[16];
#pragma unroll
    for (int pos = 0; pos < 16; pos++) {
        __half2 hv = *(const __half2*)(g_M + ((size_t)pos * NTILE + tile) * 512 + co);
        M[pos] = __half22float2(hv);
    }

    float2 P0[4], P1[4];
#pragma unroll
    for (int r = 0; r < 4; r++) {
        P0[r] = f2add(f2add(M[r * 4 + 0], M[r * 4 + 1]), M[r * 4 + 2]);
        P1[r] = f2sub(f2sub(M[r * 4 + 1], M[r * 4 + 2]), M[r * 4 + 3]);
    }
    float2 y00 = f2add(f2add(P0[0], P0[1]), P0[2]);
    float2 y10 = f2sub(f2sub(P0[1], P0[2]), P0[3]);
    float2 y01 = f2add(f2add(P1[0], P1[1]), P1[2]);
    float2 y11 = f2sub(f2sub(P1[1], P1[2]), P1[3]);

    float d0 = g_d[b * 512 + co],  d1 = g_d[b * 512 + co + 1];
    float b0 = bias[co],           b1 = bias[co + 1];
    int Y = 2 * ty, X = 2 * tx;
    float* o = out + ((size_t)((b * HW + Y) * HW + X)) * 512 + co;
    *(float2*)(o)                  = make_float2(y00.x * d0 + b0, y00.y * d1 + b1);
    *(float2*)(o + 512)            = make_float2(y01.x * d0 + b0, y01.y * d1 + b1);
    *(float2*)(o + HW * 512)       = make_float2(y10.x * d0 + b0, y10.y * d1 + b1);
    *(float2*)(o + HW * 512 + 512) = make_float2(y11.x * d0 + b0, y11.y * d1 + b1);
}

/* ------------------------------------------------------------------ */
extern "C" void kernel_launch(void* const* d_in, const int* in_sizes, int n_in,
                              void* d_out, int out_size) {
    (void)in_sizes; (void)n_in; (void)out_size;
    const float* x    = (const float*)d_in[0];
    const float* wl   = (const float*)d_in[1];
    const float* w    = (const float*)d_in[2];
    const float* bias = (const float*)d_in[3];
    const float* fcw  = (const float*)d_in[4];
    const float* fcb  = (const float*)d_in[5];
    float* out = (float*)d_out;

    style_kernel<<<dim3(NB, 4), 128>>>(wl, fcw, fcb);
    u32_kernel<<<1024, 256>>>(w);          /* also writes g_wsq */
    upack_kernel<<<2048, 256>>>();
    demod_kernel<<<dim3(NB, 4), 128>>>();
    v_kernel<<<8192, 256>>>(x);

    cudaFuncSetAttribute(gemm_kernel, cudaFuncAttributeMaxDynamicSharedMemorySize, 3 * GSTG);
    gemm_kernel<<<dim3(4, 128, 16), 256, 3 * GSTG>>>();

    inv_kernel<<<8192, 512>>>(bias, out);
}

// round 15
// speedup vs baseline: 1.1015x; 1.1015x over previous
#include <cuda_runtime.h>
#include <cuda_fp16.h>
#include <cstdint>
#include <math.h>

#define CIN   512
#define COUT  512
#define WDIM  512
#define NB    16
#define HW    64

#define CONV_COEF 0.014731391274719739f   /* 1/sqrt(9*512) */
#define FC_COEF   0.044194173824159216f   /* 1/sqrt(512)   */

#define NTILE 16384                        /* 16 imgs x 32x32 tiles */

/* ------------------------------------------------------------------ */
/* scratch (__device__ globals)                                        */
/* ------------------------------------------------------------------ */
__device__ __half g_V[(size_t)16 * 32 * 1024 * 256];
__device__ __half g_U[(size_t)16 * 512 * 512];
__device__ float  g_U32[(size_t)16 * 512 * 512];
__device__ __half g_M[(size_t)16 * NTILE * 512];
__device__ float  g_s[NB * CIN];
__device__ float  g_d[NB * COUT];
__device__ float  g_wsq[CIN * COUT];
__device__ float  g_sp[8 * NB * CIN];      /* style partials */
__device__ float  g_dp[8 * NB * COUT];     /* demod partials */

__device__ __forceinline__ uint32_t su32(const void* p) {
    uint32_t a;
    asm("{ .reg .u64 t; cvta.to.shared.u64 t, %1; cvt.u32.u64 %0, t; }" : "=r"(a) : "l"(p));
    return a;
}
__device__ __forceinline__ void cp16(uint32_t dst, const void* src) {
    asm volatile("cp.async.cg.shared.global [%0], [%1], 16;" :: "r"(dst), "l"(src));
}
__device__ __forceinline__ void cp_commit() { asm volatile("cp.async.commit_group;" ::: "memory"); }
template <int N> __device__ __forceinline__ void cp_wait() {
    asm volatile("cp.async.wait_group %0;" :: "n"(N) : "memory");
}
__device__ __forceinline__ uint32_t h2u(__half2 h) { return *(uint32_t*)&h; }

__device__ __forceinline__ void mma16(float* c, uint32_t a0, uint32_t a1,
                                      uint32_t a2, uint32_t a3,
                                      uint32_t b0, uint32_t b1) {
    asm("mma.sync.aligned.m16n8k16.row.col.f32.f16.f16.f32 "
        "{%0,%1,%2,%3},{%4,%5,%6,%7},{%8,%9},{%0,%1,%2,%3};"
        : "+f"(c[0]), "+f"(c[1]), "+f"(c[2]), "+f"(c[3])
        : "r"(a0), "r"(a1), "r"(a2), "r"(a3), "r"(b0), "r"(b1));
}

/* ------------------------------------------------------------------ */
/* style: two-stage (512 partial blocks + finisher)                    */
/* ------------------------------------------------------------------ */
__global__ void style_part(const float* __restrict__ wl,
                           const float* __restrict__ fcw) {
    __shared__ float swl[64];
    const int b  = blockIdx.x;
    const int i  = blockIdx.y * 128 + threadIdx.x;
    const int js = blockIdx.z;
    const int j0 = js * 64;
    if (threadIdx.x < 64) swl[threadIdx.x] = wl[b * WDIM + j0 + threadIdx.x];
    __syncthreads();
    float a0 = 0.f, a1 = 0.f, a2 = 0.f, a3 = 0.f;
#pragma unroll
    for (int j = 0; j < 64; j += 4) {
        a0 = fmaf(swl[j + 0], fcw[(size_t)(j0 + j + 0) * CIN + i], a0);
        a1 = fmaf(swl[j + 1], fcw[(size_t)(j0 + j + 1) * CIN + i], a1);
        a2 = fmaf(swl[j + 2], fcw[(size_t)(j0 + j + 2) * CIN + i], a2);
        a3 = fmaf(swl[j + 3], fcw[(size_t)(j0 + j + 3) * CIN + i], a3);
    }
    g_sp[(js * NB + b) * CIN + i] = (a0 + a1) + (a2 + a3);
}

__global__ void style_fin(const float* __restrict__ fcb) {
    const int b = blockIdx.x;
    const int i = threadIdx.x;
    float acc = 0.f;
#pragma unroll
    for (int js = 0; js < 8; js++)
        acc += g_sp[(js * NB + b) * CIN + i];
    g_s[b * CIN + i] = acc * FC_COEF + fcb[i] + 1.0f;
}

/* ------------------------------------------------------------------ */
/* demod: two-stage (512 partial blocks + finisher)                    */
/* ------------------------------------------------------------------ */
__global__ void demod_part() {
    __shared__ float ss[64];
    const int b   = blockIdx.x;
    const int co  = blockIdx.y * 128 + threadIdx.x;
    const int cis = blockIdx.z;
    const int c0  = cis * 64;
    if (threadIdx.x < 64) {
        float s = g_s[b * CIN + c0 + threadIdx.x];
        ss[threadIdx.x] = s * s;
    }
    __syncthreads();
    float a0 = 0.f, a1 = 0.f, a2 = 0.f, a3 = 0.f;
#pragma unroll
    for (int ci = 0; ci < 64; ci += 4) {
        a0 = fmaf(ss[ci + 0], g_wsq[(size_t)(c0 + ci + 0) * COUT + co], a0);
        a1 = fmaf(ss[ci + 1], g_wsq[(size_t)(c0 + ci + 1) * COUT + co], a1);
        a2 = fmaf(ss[ci + 2], g_wsq[(size_t)(c0 + ci + 2) * COUT + co], a2);
        a3 = fmaf(ss[ci + 3], g_wsq[(size_t)(c0 + ci + 3) * COUT + co], a3);
    }
    g_dp[(cis * NB + b) * COUT + co] = (a0 + a1) + (a2 + a3);
}

__global__ void demod_fin() {
    const int b  = blockIdx.x;
    const int co = threadIdx.x;
    float acc = 0.f;
#pragma unroll
    for (int cis = 0; cis < 8; cis++)
        acc += g_dp[(cis * NB + b) * COUT + co];
    g_d[b * COUT + co] = rsqrtf(acc * CONV_COEF * CONV_COEF + 1e-8f);
}

/* ------------------------------------------------------------------ */
/* U = G (w*coef) G^T  (fp32) + fused wsq = sum_tap w^2                */
/* ------------------------------------------------------------------ */
__global__ void u32_kernel(const float* __restrict__ w) {
    int idx = blockIdx.x * 256 + threadIdx.x;   /* 262144: (ci,co) */
    int co = idx & 511, ci = idx >> 9;
    float gm[3][3];
    float sq = 0.f;
#pragma unroll
    for (int tap = 0; tap < 9; tap++) {
        float v = w[(size_t)tap * CIN * COUT + ci * COUT + co];
        sq = fmaf(v, v, sq);
        gm[tap / 3][tap % 3] = v * CONV_COEF;
    }
    g_wsq[idx] = sq;
    float T[4][3];
#pragma unroll
    for (int c = 0; c < 3; c++) {
        T[0][c] = gm[0][c];
        T[1][c] = 0.5f * (gm[0][c] + gm[1][c] + gm[2][c]);
        T[2][c] = 0.5f * (gm[0][c] - gm[1][c] + gm[2][c]);
        T[3][c] = gm[2][c];
    }
#pragma unroll
    for (int r = 0; r < 4; r++) {
        float u0 = T[r][0];
        float u1 = 0.5f * (T[r][0] + T[r][1] + T[r][2]);
        float u2 = 0.5f * (T[r][0] - T[r][1] + T[r][2]);
        float u3 = T[r][2];
        g_U32[(((size_t)(r * 4 + 0)) * 512 + ci) * 512 + co] = u0;
        g_U32[(((size_t)(r * 4 + 1)) * 512 + ci) * 512 + co] = u1;
        g_U32[(((size_t)(r * 4 + 2)) * 512 + ci) * 512 + co] = u2;
        g_U32[(((size_t)(r * 4 + 3)) * 512 + ci) * 512 + co] = u3;
    }
}

/* pack U into m16n8k16 B-fragment order */
__global__ void upack_kernel() {
    int idx = blockIdx.x * 256 + threadIdx.x;   /* 524288 uint4 */
    int lane = idx & 31;
    int r = idx >> 5;
    int q  = r & 3;  r >>= 2;
    int wN = r & 1;  r >>= 1;
    int kg = r & 1;  r >>= 1;
    int ck = r & 15; r >>= 4;
    int nblk = r & 3;
    int pos  = r >> 2;
    int n  = nblk * 128 + wN * 64 + q * 16 + (lane >> 2);
    int k0 = ck * 32 + kg * 16 + 2 * (lane & 3);
    const float* up = g_U32 + (size_t)pos * 512 * 512;
    uint4 o;
    o.x = h2u(__floats2half2_rn(up[(size_t)k0 * 512 + n],       up[(size_t)(k0 + 1) * 512 + n]));
    o.y = h2u(__floats2half2_rn(up[(size_t)(k0 + 8) * 512 + n], up[(size_t)(k0 + 9) * 512 + n]));
    o.z = h2u(__floats2half2_rn(up[(size_t)k0 * 512 + n + 8],   up[(size_t)(k0 + 1) * 512 + n + 8]));
    o.w = h2u(__floats2half2_rn(up[(size_t)(k0 + 8) * 512 + n + 8], up[(size_t)(k0 + 9) * 512 + n + 8]));
    ((uint4*)g_U)[idx] = o;
}

/* ------------------------------------------------------------------ */
/* V = B^T (x*s) B — 2 tile-rows per block                             */
/* ------------------------------------------------------------------ */
__global__ void v_kernel(const float* __restrict__ x) {
    __shared__ float  sx[6 * 34 * 32];
    __shared__ __half sbuf[16 * 2 * 256];
    int idx = blockIdx.x;
    const int ckg = idx & 15;  idx >>= 4;
    const int h   = idx & 1;   idx >>= 1;
    const int typ = idx & 15;
    const int b   = idx >> 4;
    const int tid = threadIdx.x;

    const uint32_t sxa = su32(sx);
    {
        const int iyb = 4 * typ - 1, ixb = 32 * h - 1;
#pragma unroll
        for (int j = 0; j < 7; j++) {
            int i = tid + j * 256;
            if (i < 1632) {
                int q  = i & 7;
                int rc = i >> 3;
                int row = rc / 34, col = rc - 34 * row;
                int iy = iyb + row, ix = ixb + col;
                uint32_t dst = sxa + (rc * 32 + q * 4) * 4;
                if ((unsigned)iy < HW && (unsigned)ix < HW) {
                    cp16(dst, x + ((size_t)((b * HW + iy) * HW + ix)) * CIN + ckg * 32 + q * 4);
                } else {
                    *(float4*)((char*)sx + (rc * 32 + q * 4) * 4) = make_float4(0.f, 0.f, 0.f, 0.f);
                }
            }
        }
    }
    cp_commit();
    cp_wait<0>();
    __syncthreads();

#pragma unroll
    for (int p = 0; p < 2; p++) {
        if (p) __syncthreads();
#pragma unroll
        for (int u = 0; u < 2; u++) {
            int uid = tid + 256 * u;
            int tl = uid >> 5, ch = uid & 31;
            float s = g_s[b * 512 + ckg * 32 + ch];
            float d[4][4];
#pragma unroll
            for (int r = 0; r < 4; r++)
#pragma unroll
                for (int c = 0; c < 4; c++)
                    d[r][c] = sx[((2 * p + r) * 34 + 2 * tl + c) * 32 + ch] * s;
            float tt[4][4];
#pragma unroll
            for (int c = 0; c < 4; c++) {
                tt[0][c] = d[0][c] - d[2][c];
                tt[1][c] = d[1][c] + d[2][c];
                tt[2][c] = d[2][c] - d[1][c];
                tt[3][c] = d[1][c] - d[3][c];
            }
            int g = tl & 7, hh = tl >> 3;
            int kg = ch >> 4, kk = ch & 15, j = kk >> 1;
            int off = g * 64 + (j & 3) * 16 + (j >> 2) * 8 + hh * 4 + (kk & 1) * 2;
#pragma unroll
            for (int i = 0; i < 4; i++) {
                float v0 = tt[i][0] - tt[i][2];
                float v1 = tt[i][1] + tt[i][2];
                float v2 = tt[i][2] - tt[i][1];
                float v3 = tt[i][1] - tt[i][3];
                char* pl = (char*)sbuf + kg * 512;
                *(__half*)(pl + (i * 4 + 0) * 1024 + off) = __float2half(v0);
                *(__half*)(pl + (i * 4 + 1) * 1024 + off) = __float2half(v1);
                *(__half*)(pl + (i * 4 + 2) * 1024 + off) = __float2half(v2);
                *(__half*)(pl + (i * 4 + 3) * 1024 + off) = __float2half(v3);
            }
        }
        __syncthreads();
        const int mblk = b * 64 + (2 * typ + p) * 2 + h;
#pragma unroll
        for (int j = 0; j < 4; j++) {
            int cidx = tid + 256 * j;
            int plane = cidx >> 5, o16 = (cidx & 31) * 16;
            int pos = plane >> 1, kg = plane & 1;
            char* dst = (char*)g_V + (((size_t)(pos * 32 + ckg * 2 + kg)) * 1024 + mblk) * 512 + o16;
            *(uint4*)dst = *(uint4*)((char*)sbuf + plane * 512 + o16);
        }
    }
}

/* ------------------------------------------------------------------ */
/* GEMM per pos: M = V U ; CTA 128x128, warp 64x32, K-chunk 64         */
/* ------------------------------------------------------------------ */
#define GSTG 32768

__device__ __forceinline__ void g_load(uint32_t sb, const char* Vsrc, const char* Usrc,
                                       int s, int tid) {
#pragma unroll
    for (int j = 0; j < 8; j++) {
        int i = tid + 256 * j;
        if (i < 1024) {
            int kg = i >> 8, mo = i & 255;
            const char* src = Vsrc + ((size_t)(s * 4 + kg) * 1024 + (mo >> 5)) * 512 + (mo & 31) * 16;
            cp16(sb + kg * 4096 + mo * 16, src);
        } else {
            int i2 = i - 1024;
            cp16(sb + 16384 + i2 * 16, Usrc + (size_t)s * 16384 + i2 * 16);
        }
    }
}

__global__ __launch_bounds__(256, 2)
void gemm_kernel() {
    extern __shared__ char sm[];
    const int tid  = threadIdx.x;
    const int warp = tid >> 5;
    const int lane = tid & 31;
    const int g = lane >> 2, t = lane & 3;
    const int wn = warp & 3, wm = warp >> 2;
    const int nblk = blockIdx.x;
    const int mby  = blockIdx.y;
    const int pos  = blockIdx.z;

    const char* Vsrc = (const char*)g_V + ((size_t)pos * 32 * 1024 + (size_t)mby * 8) * 512;
    const char* Usrc = (const char*)g_U + (size_t)((pos * 4 + nblk) * 16) * 8192;
    const uint32_t sb = su32(sm);

    float acc[4][4][4];
#pragma unroll
    for (int mi = 0; mi < 4; mi++)
#pragma unroll
        for (int ni = 0; ni < 4; ni++)
#pragma unroll
            for (int r = 0; r < 4; r++) acc[mi][ni][r] = 0.f;

    g_load(sb, Vsrc, Usrc, 0, tid); cp_commit();
    g_load(sb + GSTG, Vsrc, Usrc, 1, tid); cp_commit();

    for (int s = 0; s < 8; s++) {
        cp_wait<1>();
        __syncthreads();
        const int s2 = s + 2;
        if (s2 < 8)
            g_load(sb + (s2 % 3) * GSTG, Vsrc, Usrc, s2, tid);
        cp_commit();

        const char* st = sm + (s % 3) * GSTG;
#pragma unroll
        for (int j = 0; j < 4; j++) {
            const char* ab = st + j * 4096 + wm * 2048 + g * 64 + t * 16;
            float4 Af[4];
#pragma unroll
            for (int mi = 0; mi < 4; mi++)
                Af[mi] = *(const float4*)(ab + mi * 512);
            const char* bb = st + 16384 + (j >> 1) * 8192 + (j & 1) * 4096
                           + (wn >> 1) * 2048 + (wn & 1) * 1024 + lane * 16;
            float4 Bf[2];
            Bf[0] = *(const float4*)bb;
            Bf[1] = *(const float4*)(bb + 512);
#pragma unroll
            for (int mi = 0; mi < 4; mi++)
#pragma unroll
                for (int ni = 0; ni < 4; ni++) {
                    const float4& B = Bf[ni >> 1];
                    uint32_t b0 = __float_as_uint((ni & 1) ? B.z : B.x);
                    uint32_t b1 = __float_as_uint((ni & 1) ? B.w : B.y);
                    mma16(acc[mi][ni],
                          __float_as_uint(Af[mi].x), __float_as_uint(Af[mi].y),
                          __float_as_uint(Af[mi].z), __float_as_uint(Af[mi].w),
                          b0, b1);
                }
        }
    }

    __half* Mp = g_M + (size_t)pos * NTILE * 512;
    const int m0 = mby * 128 + wm * 64;
    const int c0 = nblk * 128 + wn * 32;
#pragma unroll
    for (int mi = 0; mi < 4; mi++) {
        int r0 = m0 + mi * 16 + g;
#pragma unroll
        for (int ni = 0; ni < 4; ni++) {
            int cc = c0 + (ni >> 1) * 16 + (ni & 1) * 8 + t * 2;
            *(uint32_t*)(Mp + (size_t)r0 * 512 + cc) =
                h2u(__floats2half2_rn(acc[mi][ni][0], acc[mi][ni][1]));
            *(uint32_t*)(Mp + (size_t)(r0 + 8) * 512 + cc) =
                h2u(__floats2half2_rn(acc[mi][ni][2], acc[mi][ni][3]));
        }
    }
}

/* ------------------------------------------------------------------ */
/* inverse transform: y = A^T M A, * demod + bias — 2 co per thread    */
/* ------------------------------------------------------------------ */
__device__ __forceinline__ float2 f2add(float2 a, float2 b) {
    return make_float2(a.x + b.x, a.y + b.y);
}
__device__ __forceinline__ float2 f2sub(float2 a, float2 b) {
    return make_float2(a.x - b.x, a.y - b.y);
}

__global__ void inv_kernel(const float* __restrict__ bias, float* __restrict__ out) {
    int Wu = blockIdx.x * 16 + (threadIdx.x >> 5);
    int lane = threadIdx.x & 31;
    int tile = Wu >> 3, cog = Wu & 7;
    int co = cog * 64 + lane * 2;
    int b = tile >> 10, tl = tile & 1023, ty = tl >> 5, tx = tl & 31;

    float2 M[16];
#pragma unroll
    for (int pos = 0; pos < 16; pos++) {
        __half2 hv = *(const __half2*)(g_M + ((size_t)pos * NTILE + tile) * 512 + co);
        M[pos] = __half22float2(hv);
    }

    float2 P0[4], P1[4];
#pragma unroll
    for (int r = 0; r < 4; r++) {
        P0[r] = f2add(f2add(M[r * 4 + 0], M[r * 4 + 1]), M[r * 4 + 2]);
        P1[r] = f2sub(f2sub(M[r * 4 + 1], M[r * 4 + 2]), M[r * 4 + 3]);
    }
    float2 y00 = f2add(f2add(P0[0], P0[1]), P0[2]);
    float2 y10 = f2sub(f2sub(P0[1], P0[2]), P0[3]);
    float2 y01 = f2add(f2add(P1[0], P1[1]), P1[2]);
    float2 y11 = f2sub(f2sub(P1[1], P1[2]), P1[3]);

    float d0 = g_d[b * 512 + co],  d1 = g_d[b * 512 + co + 1];
    float b0 = bias[co],           b1 = bias[co + 1];
    int Y = 2 * ty, X = 2 * tx;
    float* o = out + ((size_t)((b * HW + Y) * HW + X)) * 512 + co;
    *(float2*)(o)                  = make_float2(y00.x * d0 + b0, y00.y * d1 + b1);
    *(float2*)(o + 512)            = make_float2(y01.x * d0 + b0, y01.y * d1 + b1);
    *(float2*)(o + HW * 512)       = make_float2(y10.x * d0 + b0, y10.y * d1 + b1);
    *(float2*)(o + HW * 512 + 512) = make_float2(y11.x * d0 + b0, y11.y * d1 + b1);
}

/* ------------------------------------------------------------------ */
extern "C" void kernel_launch(void* const* d_in, const int* in_sizes, int n_in,
                              void* d_out, int out_size) {
    (void)in_sizes; (void)n_in; (void)out_size;
    const float* x    = (const float*)d_in[0];
    const float* wl   = (const float*)d_in[1];
    const float* w    = (const float*)d_in[2];
    const float* bias = (const float*)d_in[3];
    const float* fcw  = (const float*)d_in[4];
    const float* fcb  = (const float*)d_in[5];
    float* out = (float*)d_out;

    style_part<<<dim3(NB, 4, 8), 128>>>(wl, fcw);
    style_fin<<<NB, CIN>>>(fcb);
    u32_kernel<<<1024, 256>>>(w);          /* also writes g_wsq */
    upack_kernel<<<2048, 256>>>();
    demod_part<<<dim3(NB, 4, 8), 128>>>();
    demod_fin<<<NB, COUT>>>();
    v_kernel<<<8192, 256>>>(x);

    cudaFuncSetAttribute(gemm_kernel, cudaFuncAttributeMaxDynamicSharedMemorySize, 3 * GSTG);
    gemm_kernel<<<dim3(4, 128, 16), 256, 3 * GSTG>>>();

    inv_kernel<<<8192, 512>>>(bias, out);
}

// round 16
// speedup vs baseline: 1.1092x; 1.0070x over previous
#include <cuda_runtime.h>
#include <cuda_fp16.h>
#include <cstdint>
#include <math.h>

#define CIN   512
#define COUT  512
#define WDIM  512
#define NB    16
#define HW    64

#define CONV_COEF 0.014731391274719739f   /* 1/sqrt(9*512) */
#define FC_COEF   0.044194173824159216f   /* 1/sqrt(512)   */

#define NTILE 16384                        /* 16 imgs x 32x32 tiles */

/* ------------------------------------------------------------------ */
/* scratch (__device__ globals)                                        */
/* ------------------------------------------------------------------ */
__device__ __half g_V[(size_t)16 * 32 * 1024 * 256];
__device__ __half g_U[(size_t)16 * 512 * 512];
__device__ __half g_M[(size_t)16 * NTILE * 512];
__device__ float  g_s[NB * CIN];
__device__ float  g_d[NB * COUT];
__device__ float  g_wsq[CIN * COUT];
__device__ float  g_sp[8 * NB * CIN];      /* style partials */
__device__ float  g_dp[8 * NB * COUT];     /* demod partials */

__device__ __forceinline__ uint32_t su32(const void* p) {
    uint32_t a;
    asm("{ .reg .u64 t; cvta.to.shared.u64 t, %1; cvt.u32.u64 %0, t; }" : "=r"(a) : "l"(p));
    return a;
}
__device__ __forceinline__ void cp16(uint32_t dst, const void* src) {
    asm volatile("cp.async.cg.shared.global [%0], [%1], 16;" :: "r"(dst), "l"(src));
}
__device__ __forceinline__ void cp_commit() { asm volatile("cp.async.commit_group;" ::: "memory"); }
template <int N> __device__ __forceinline__ void cp_wait() {
    asm volatile("cp.async.wait_group %0;" :: "n"(N) : "memory");
}
__device__ __forceinline__ uint32_t h2u(__half2 h) { return *(uint32_t*)&h; }

__device__ __forceinline__ void mma16(float* c, uint32_t a0, uint32_t a1,
                                      uint32_t a2, uint32_t a3,
                                      uint32_t b0, uint32_t b1) {
    asm("mma.sync.aligned.m16n8k16.row.col.f32.f16.f16.f32 "
        "{%0,%1,%2,%3},{%4,%5,%6,%7},{%8,%9},{%0,%1,%2,%3};"
        : "+f"(c[0]), "+f"(c[1]), "+f"(c[2]), "+f"(c[3])
        : "r"(a0), "r"(a1), "r"(a2), "r"(a3), "r"(b0), "r"(b1));
}

/* ------------------------------------------------------------------ */
/* style: two-stage (512 partial blocks + finisher)                    */
/* ------------------------------------------------------------------ */
__global__ void style_part(const float* __restrict__ wl,
                           const float* __restrict__ fcw) {
    __shared__ float swl[64];
    const int b  = blockIdx.x;
    const int i  = blockIdx.y * 128 + threadIdx.x;
    const int js = blockIdx.z;
    const int j0 = js * 64;
    if (threadIdx.x < 64) swl[threadIdx.x] = wl[b * WDIM + j0 + threadIdx.x];
    __syncthreads();
    float a0 = 0.f, a1 = 0.f, a2 = 0.f, a3 = 0.f;
#pragma unroll
    for (int j = 0; j < 64; j += 4) {
        a0 = fmaf(swl[j + 0], fcw[(size_t)(j0 + j + 0) * CIN + i], a0);
        a1 = fmaf(swl[j + 1], fcw[(size_t)(j0 + j + 1) * CIN + i], a1);
        a2 = fmaf(swl[j + 2], fcw[(size_t)(j0 + j + 2) * CIN + i], a2);
        a3 = fmaf(swl[j + 3], fcw[(size_t)(j0 + j + 3) * CIN + i], a3);
    }
    g_sp[(js * NB + b) * CIN + i] = (a0 + a1) + (a2 + a3);
}

__global__ void style_fin(const float* __restrict__ fcb) {
    const int b = blockIdx.x;
    const int i = threadIdx.x;
    float acc = 0.f;
#pragma unroll
    for (int js = 0; js < 8; js++)
        acc += g_sp[(js * NB + b) * CIN + i];
    g_s[b * CIN + i] = acc * FC_COEF + fcb[i] + 1.0f;
}

/* ------------------------------------------------------------------ */
/* demod: two-stage (512 partial blocks + finisher)                    */
/* ------------------------------------------------------------------ */
__global__ void demod_part() {
    __shared__ float ss[64];
    const int b   = blockIdx.x;
    const int co  = blockIdx.y * 128 + threadIdx.x;
    const int cis = blockIdx.z;
    const int c0  = cis * 64;
    if (threadIdx.x < 64) {
        float s = g_s[b * CIN + c0 + threadIdx.x];
        ss[threadIdx.x] = s * s;
    }
    __syncthreads();
    float a0 = 0.f, a1 = 0.f, a2 = 0.f, a3 = 0.f;
#pragma unroll
    for (int ci = 0; ci < 64; ci += 4) {
        a0 = fmaf(ss[ci + 0], g_wsq[(size_t)(c0 + ci + 0) * COUT + co], a0);
        a1 = fmaf(ss[ci + 1], g_wsq[(size_t)(c0 + ci + 1) * COUT + co], a1);
        a2 = fmaf(ss[ci + 2], g_wsq[(size_t)(c0 + ci + 2) * COUT + co], a2);
        a3 = fmaf(ss[ci + 3], g_wsq[(size_t)(c0 + ci + 3) * COUT + co], a3);
    }
    g_dp[(cis * NB + b) * COUT + co] = (a0 + a1) + (a2 + a3);
}

__global__ void demod_fin() {
    const int b  = blockIdx.x;
    const int co = threadIdx.x;
    float acc = 0.f;
#pragma unroll
    for (int cis = 0; cis < 8; cis++)
        acc += g_dp[(cis * NB + b) * COUT + co];
    g_d[b * COUT + co] = rsqrtf(acc * CONV_COEF * CONV_COEF + 1e-8f);
}

/* ------------------------------------------------------------------ */
/* fused: U = G (w*coef) G^T -> fp16 packed B-fragment order + wsq     */
/* 256 blocks = (ct 16 ci-tiles) x (cc 16 co-tiles), 256 threads       */
/* smem sU2[pos][ci-pair][co] : uint = half2(U[2p], U[2p+1])           */
/* ------------------------------------------------------------------ */
__global__ void uw_kernel(const float* __restrict__ w) {
    __shared__ uint32_t sU2[16][16][33];        /* 33792 B */
    const int ct = blockIdx.x >> 4, cc = blockIdx.x & 15;
    const int co_l = threadIdx.x & 31;
    const int ci_b = threadIdx.x >> 5;          /* 0..7 */
    const int ci0 = ct * 32, co0 = cc * 32;
    const int co = co0 + co_l;

#pragma unroll
    for (int jp = 0; jp < 2; jp++) {            /* ci pair within thread's 4 */
        float Upair[2][16];
#pragma unroll
        for (int e = 0; e < 2; e++) {
            int ci = ci0 + ci_b * 4 + jp * 2 + e;
            float gm[3][3];
            float sq = 0.f;
#pragma unroll
            for (int tap = 0; tap < 9; tap++) {
                float v = w[(size_t)tap * CIN * COUT + (size_t)ci * COUT + co];
                sq = fmaf(v, v, sq);
                gm[tap / 3][tap % 3] = v * CONV_COEF;
            }
            g_wsq[(size_t)ci * COUT + co] = sq;
            float T[4][3];
#pragma unroll
            for (int c = 0; c < 3; c++) {
                T[0][c] = gm[0][c];
                T[1][c] = 0.5f * (gm[0][c] + gm[1][c] + gm[2][c]);
                T[2][c] = 0.5f * (gm[0][c] - gm[1][c] + gm[2][c]);
                T[3][c] = gm[2][c];
            }
#pragma unroll
            for (int r = 0; r < 4; r++) {
                Upair[e][r * 4 + 0] = T[r][0];
                Upair[e][r * 4 + 1] = 0.5f * (T[r][0] + T[r][1] + T[r][2]);
                Upair[e][r * 4 + 2] = 0.5f * (T[r][0] - T[r][1] + T[r][2]);
                Upair[e][r * 4 + 3] = T[r][2];
            }
        }
        int pair = ci_b * 2 + jp;               /* 0..15 */
#pragma unroll
        for (int pos = 0; pos < 16; pos++)
            sU2[pos][pair][co_l] = h2u(__floats2half2_rn(Upair[0][pos], Upair[1][pos]));
    }
    __syncthreads();

    /* pack phase: 2048 uint4 per block, 8 per thread */
    const int lane = threadIdx.x & 31;
    const int grp  = threadIdx.x >> 5;
    const int nblk = cc >> 2, wN = (cc >> 1) & 1;
    const int g = lane >> 2, tt = lane & 3;
#pragma unroll
    for (int i = 0; i < 8; i++) {
        int local = grp + 8 * i;                /* 0..63 = pos*4 + kg*2 + qs */
        int qs = local & 1, kg = (local >> 1) & 1, pos = local >> 2;
        int q = 2 * (cc & 1) + qs;
        int pr = kg * 8 + tt;
        int n_l = qs * 16 + g;
        uint4 o;
        o.x = sU2[pos][pr][n_l];
        o.y = sU2[pos][pr + 4][n_l];
        o.z = sU2[pos][pr][n_l + 8];
        o.w = sU2[pos][pr + 4][n_l + 8];
        size_t gidx = ((((size_t)(pos * 4 + nblk) * 16 + ct) * 2 + kg) * 2 + wN) * 4 + q;
        ((uint4*)g_U)[gidx * 32 + lane] = o;
    }
}

/* ------------------------------------------------------------------ */
/* V = B^T (x*s) B — 2 tile-rows per block                             */
/* ------------------------------------------------------------------ */
__global__ void v_kernel(const float* __restrict__ x) {
    __shared__ float  sx[6 * 34 * 32];
    __shared__ __half sbuf[16 * 2 * 256];
    int idx = blockIdx.x;
    const int ckg = idx & 15;  idx >>= 4;
    const int h   = idx & 1;   idx >>= 1;
    const int typ = idx & 15;
    const int b   = idx >> 4;
    const int tid = threadIdx.x;

    const uint32_t sxa = su32(sx);
    {
        const int iyb = 4 * typ - 1, ixb = 32 * h - 1;
#pragma unroll
        for (int j = 0; j < 7; j++) {
            int i = tid + j * 256;
            if (i < 1632) {
                int q  = i & 7;
                int rc = i >> 3;
                int row = rc / 34, col = rc - 34 * row;
                int iy = iyb + row, ix = ixb + col;
                uint32_t dst = sxa + (rc * 32 + q * 4) * 4;
                if ((unsigned)iy < HW && (unsigned)ix < HW) {
                    cp16(dst, x + ((size_t)((b * HW + iy) * HW + ix)) * CIN + ckg * 32 + q * 4);
                } else {
                    *(float4*)((char*)sx + (rc * 32 + q * 4) * 4) = make_float4(0.f, 0.f, 0.f, 0.f);
                }
            }
        }
    }
    cp_commit();
    cp_wait<0>();
    __syncthreads();

#pragma unroll
    for (int p = 0; p < 2; p++) {
        if (p) __syncthreads();
#pragma unroll
        for (int u = 0; u < 2; u++) {
            int uid = tid + 256 * u;
            int tl = uid >> 5, ch = uid & 31;
            float s = g_s[b * 512 + ckg * 32 + ch];
            float d[4][4];
#pragma unroll
            for (int r = 0; r < 4; r++)
#pragma unroll
                for (int c = 0; c < 4; c++)
                    d[r][c] = sx[((2 * p + r) * 34 + 2 * tl + c) * 32 + ch] * s;
            float tt[4][4];
#pragma unroll
            for (int c = 0; c < 4; c++) {
                tt[0][c] = d[0][c] - d[2][c];
                tt[1][c] = d[1][c] + d[2][c];
                tt[2][c] = d[2][c] - d[1][c];
                tt[3][c] = d[1][c] - d[3][c];
            }
            int g = tl & 7, hh = tl >> 3;
            int kg = ch >> 4, kk = ch & 15, j = kk >> 1;
            int off = g * 64 + (j & 3) * 16 + (j >> 2) * 8 + hh * 4 + (kk & 1) * 2;
#pragma unroll
            for (int i = 0; i < 4; i++) {
                float v0 = tt[i][0] - tt[i][2];
                float v1 = tt[i][1] + tt[i][2];
                float v2 = tt[i][2] - tt[i][1];
                float v3 = tt[i][1] - tt[i][3];
                char* pl = (char*)sbuf + kg * 512;
                *(__half*)(pl + (i * 4 + 0) * 1024 + off) = __float2half(v0);
                *(__half*)(pl + (i * 4 + 1) * 1024 + off) = __float2half(v1);
                *(__half*)(pl + (i * 4 + 2) * 1024 + off) = __float2half(v2);
                *(__half*)(pl + (i * 4 + 3) * 1024 + off) = __float2half(v3);
            }
        }
        __syncthreads();
        const int mblk = b * 64 + (2 * typ + p) * 2 + h;
#pragma unroll
        for (int j = 0; j < 4; j++) {
            int cidx = tid + 256 * j;
            int plane = cidx >> 5, o16 = (cidx & 31) * 16;
            int pos = plane >> 1, kg = plane & 1;
            char* dst = (char*)g_V + (((size_t)(pos * 32 + ckg * 2 + kg)) * 1024 + mblk) * 512 + o16;
            *(uint4*)dst = *(uint4*)((char*)sbuf + plane * 512 + o16);
        }
    }
}

/* ------------------------------------------------------------------ */
/* GEMM per pos: M = V U ; CTA 128x128, warp 64x32, K-chunk 64         */
/* ------------------------------------------------------------------ */
#define GSTG 32768

__device__ __forceinline__ void g_load(uint32_t sb, const char* Vsrc, const char* Usrc,
                                       int s, int tid) {
#pragma unroll
    for (int j = 0; j < 8; j++) {
        int i = tid + 256 * j;
        if (i < 1024) {
            int kg = i >> 8, mo = i & 255;
            const char* src = Vsrc + ((size_t)(s * 4 + kg) * 1024 + (mo >> 5)) * 512 + (mo & 31) * 16;
            cp16(sb + kg * 4096 + mo * 16, src);
        } else {
            int i2 = i - 1024;
            cp16(sb + 16384 + i2 * 16, Usrc + (size_t)s * 16384 + i2 * 16);
        }
    }
}

__global__ __launch_bounds__(256, 2)
void gemm_kernel() {
    extern __shared__ char sm[];
    const int tid  = threadIdx.x;
    const int warp = tid >> 5;
    const int lane = tid & 31;
    const int g = lane >> 2, t = lane & 3;
    const int wn = warp & 3, wm = warp >> 2;
    const int nblk = blockIdx.x;
    const int mby  = blockIdx.y;
    const int pos  = blockIdx.z;

    const char* Vsrc = (const char*)g_V + ((size_t)pos * 32 * 1024 + (size_t)mby * 8) * 512;
    const char* Usrc = (const char*)g_U + (size_t)((pos * 4 + nblk) * 16) * 8192;
    const uint32_t sb = su32(sm);

    float acc[4][4][4];
#pragma unroll
    for (int mi = 0; mi < 4; mi++)
#pragma unroll
        for (int ni = 0; ni < 4; ni++)
#pragma unroll
            for (int r = 0; r < 4; r++) acc[mi][ni][r] = 0.f;

    g_load(sb, Vsrc, Usrc, 0, tid); cp_commit();
    g_load(sb + GSTG, Vsrc, Usrc, 1, tid); cp_commit();

    for (int s = 0; s < 8; s++) {
        cp_wait<1>();
        __syncthreads();
        const int s2 = s + 2;
        if (s2 < 8)
            g_load(sb + (s2 % 3) * GSTG, Vsrc, Usrc, s2, tid);
        cp_commit();

        const char* st = sm + (s % 3) * GSTG;
#pragma unroll
        for (int j = 0; j < 4; j++) {
            const char* ab = st + j * 4096 + wm * 2048 + g * 64 + t * 16;
            float4 Af[4];
#pragma unroll
            for (int mi = 0; mi < 4; mi++)
                Af[mi] = *(const float4*)(ab + mi * 512);
            const char* bb = st + 16384 + (j >> 1) * 8192 + (j & 1) * 4096
                           + (wn >> 1) * 2048 + (wn & 1) * 1024 + lane * 16;
            float4 Bf[2];
            Bf[0] = *(const float4*)bb;
            Bf[1] = *(const float4*)(bb + 512);
#pragma unroll
            for (int mi = 0; mi < 4; mi++)
#pragma unroll
                for (int ni = 0; ni < 4; ni++) {
                    const float4& B = Bf[ni >> 1];
                    uint32_t b0 = __float_as_uint((ni & 1) ? B.z : B.x);
                    uint32_t b1 = __float_as_uint((ni & 1) ? B.w : B.y);
                    mma16(acc[mi][ni],
                          __float_as_uint(Af[mi].x), __float_as_uint(Af[mi].y),
                          __float_as_uint(Af[mi].z), __float_as_uint(Af[mi].w),
                          b0, b1);
                }
        }
    }

    __half* Mp = g_M + (size_t)pos * NTILE * 512;
    const int m0 = mby * 128 + wm * 64;
    const int c0 = nblk * 128 + wn * 32;
#pragma unroll
    for (int mi = 0; mi < 4; mi++) {
        int r0 = m0 + mi * 16 + g;
#pragma unroll
        for (int ni = 0; ni < 4; ni++) {
            int cc = c0 + (ni >> 1) * 16 + (ni & 1) * 8 + t * 2;
            *(uint32_t*)(Mp + (size_t)r0 * 512 + cc) =
                h2u(__floats2half2_rn(acc[mi][ni][0], acc[mi][ni][1]));
            *(uint32_t*)(Mp + (size_t)(r0 + 8) * 512 + cc) =
                h2u(__floats2half2_rn(acc[mi][ni][2], acc[mi][ni][3]));
        }
    }
}

/* ------------------------------------------------------------------ */
/* inverse transform: y = A^T M A, * demod + bias — 2 co per thread    */
/* ------------------------------------------------------------------ */
__device__ __forceinline__ float2 f2add(float2 a, float2 b) {
    return make_float2(a.x + b.x, a.y + b.y);
}
__device__ __forceinline__ float2 f2sub(float2 a, float2 b) {
    return make_float2(a.x - b.x, a.y - b.y);
}

__global__ void inv_kernel(const float* __restrict__ bias, float* __restrict__ out) {
    int Wu = blockIdx.x * 16 + (threadIdx.x >> 5);
    int lane = threadIdx.x & 31;
    int tile = Wu >> 3, cog = Wu & 7;
    int co = cog * 64 + lane * 2;
    int b = tile >> 10, tl = tile & 1023, ty = tl >> 5, tx = tl & 31;

    float2 M[16];
#pragma unroll
    for (int pos = 0; pos < 16; pos++) {
        __half2 hv = *(const __half2*)(g_M + ((size_t)pos * NTILE + tile) * 512 + co);
        M[pos] = __half22float2(hv);
    }

    float2 P0[4], P1[4];
#pragma unroll
    for (int r = 0; r < 4; r++) {
        P0[r] = f2add(f2add(M[r * 4 + 0], M[r * 4 + 1]), M[r * 4 + 2]);
        P1[r] = f2sub(f2sub(M[r * 4 + 1], M[r * 4 + 2]), M[r * 4 + 3]);
    }
    float2 y00 = f2add(f2add(P0[0], P0[1]), P0[2]);
    float2 y10 = f2sub(f2sub(P0[1], P0[2]), P0[3]);
    float2 y01 = f2add(f2add(P1[0], P1[1]), P1[2]);
    float2 y11 = f2sub(f2sub(P1[1], P1[2]), P1[3]);

    float d0 = g_d[b * 512 + co],  d1 = g_d[b * 512 + co + 1];
    float b0 = bias[co],           b1 = bias[co + 1];
    int Y = 2 * ty, X = 2 * tx;
    float* o = out + ((size_t)((b * HW + Y) * HW + X)) * 512 + co;
    *(float2*)(o)                  = make_float2(y00.x * d0 + b0, y00.y * d1 + b1);
    *(float2*)(o + 512)            = make_float2(y01.x * d0 + b0, y01.y * d1 + b1);
    *(float2*)(o + HW * 512)       = make_float2(y10.x * d0 + b0, y10.y * d1 + b1);
    *(float2*)(o + HW * 512 + 512) = make_float2(y11.x * d0 + b0, y11.y * d1 + b1);
}

/* ------------------------------------------------------------------ */
extern "C" void kernel_launch(void* const* d_in, const int* in_sizes, int n_in,
                              void* d_out, int out_size) {
    (void)in_sizes; (void)n_in; (void)out_size;
    const float* x    = (const float*)d_in[0];
    const float* wl   = (const float*)d_in[1];
    const float* w    = (const float*)d_in[2];
    const float* bias = (const float*)d_in[3];
    const float* fcw  = (const float*)d_in[4];
    const float* fcb  = (const float*)d_in[5];
    float* out = (float*)d_out;

    uw_kernel<<<256, 256>>>(w);            /* fused U-pack + wsq */
    style_part<<<dim3(NB, 4, 8), 128>>>(wl, fcw);
    style_fin<<<NB, CIN>>>(fcb);
    demod_part<<<dim3(NB, 4, 8), 128>>>();
    demod_fin<<<NB, COUT>>>();
    v_kernel<<<8192, 256>>>(x);

    cudaFuncSetAttribute(gemm_kernel, cudaFuncAttributeMaxDynamicSharedMemorySize, 3 * GSTG);
    gemm_kernel<<<dim3(4, 128, 16), 256, 3 * GSTG>>>();

    inv_kernel<<<8192, 512>>>(bias, out);
}

// round 17
// speedup vs baseline: 1.1147x; 1.0049x over previous
#include <cuda_runtime.h>
#include <cuda_fp16.h>
#include <cstdint>
#include <math.h>

#define CIN   512
#define COUT  512
#define WDIM  512
#define NB    16
#define HW    64

#define CONV_COEF 0.014731391274719739f   /* 1/sqrt(9*512) */
#define FC_COEF   0.044194173824159216f   /* 1/sqrt(512)   */

#define NTILE 16384                        /* 16 imgs x 32x32 tiles */

/* ------------------------------------------------------------------ */
/* scratch (__device__ globals)                                        */
/* ------------------------------------------------------------------ */
__device__ __half g_V[(size_t)16 * 32 * 1024 * 256];
__device__ __half g_U[(size_t)16 * 512 * 512];
__device__ __half g_M[(size_t)16 * NTILE * 512];
__device__ float  g_s[NB * CIN];
__device__ float  g_d[NB * COUT];
__device__ float  g_wsq[CIN * COUT];
__device__ float  g_sp[8 * NB * CIN];      /* style partials */
__device__ float  g_dp[8 * NB * COUT];     /* demod partials */

__device__ __forceinline__ uint32_t su32(const void* p) {
    uint32_t a;
    asm("{ .reg .u64 t; cvta.to.shared.u64 t, %1; cvt.u32.u64 %0, t; }" : "=r"(a) : "l"(p));
    return a;
}
__device__ __forceinline__ void cp16(uint32_t dst, const void* src) {
    asm volatile("cp.async.cg.shared.global [%0], [%1], 16;" :: "r"(dst), "l"(src));
}
__device__ __forceinline__ void cp_commit() { asm volatile("cp.async.commit_group;" ::: "memory"); }
template <int N> __device__ __forceinline__ void cp_wait() {
    asm volatile("cp.async.wait_group %0;" :: "n"(N) : "memory");
}
__device__ __forceinline__ uint32_t h2u(__half2 h) { return *(uint32_t*)&h; }

__device__ __forceinline__ void mma16(float* c, uint32_t a0, uint32_t a1,
                                      uint32_t a2, uint32_t a3,
                                      uint32_t b0, uint32_t b1) {
    asm("mma.sync.aligned.m16n8k16.row.col.f32.f16.f16.f32 "
        "{%0,%1,%2,%3},{%4,%5,%6,%7},{%8,%9},{%0,%1,%2,%3};"
        : "+f"(c[0]), "+f"(c[1]), "+f"(c[2]), "+f"(c[3])
        : "r"(a0), "r"(a1), "r"(a2), "r"(a3), "r"(b0), "r"(b1));
}

/* ------------------------------------------------------------------ */
/* style: two-stage (512 partial blocks + finisher)                    */
/* ------------------------------------------------------------------ */
__global__ void style_part(const float* __restrict__ wl,
                           const float* __restrict__ fcw) {
    __shared__ float swl[64];
    const int b  = blockIdx.x;
    const int i  = blockIdx.y * 128 + threadIdx.x;
    const int js = blockIdx.z;
    const int j0 = js * 64;
    if (threadIdx.x < 64) swl[threadIdx.x] = wl[b * WDIM + j0 + threadIdx.x];
    __syncthreads();
    float a0 = 0.f, a1 = 0.f, a2 = 0.f, a3 = 0.f;
#pragma unroll
    for (int j = 0; j < 64; j += 4) {
        a0 = fmaf(swl[j + 0], fcw[(size_t)(j0 + j + 0) * CIN + i], a0);
        a1 = fmaf(swl[j + 1], fcw[(size_t)(j0 + j + 1) * CIN + i], a1);
        a2 = fmaf(swl[j + 2], fcw[(size_t)(j0 + j + 2) * CIN + i], a2);
        a3 = fmaf(swl[j + 3], fcw[(size_t)(j0 + j + 3) * CIN + i], a3);
    }
    g_sp[(js * NB + b) * CIN + i] = (a0 + a1) + (a2 + a3);
}

__global__ void style_fin(const float* __restrict__ fcb) {
    const int b = blockIdx.x;
    const int i = threadIdx.x;
    float acc = 0.f;
#pragma unroll
    for (int js = 0; js < 8; js++)
        acc += g_sp[(js * NB + b) * CIN + i];
    g_s[b * CIN + i] = acc * FC_COEF + fcb[i] + 1.0f;
}

/* ------------------------------------------------------------------ */
/* demod: two-stage (512 partial blocks + finisher)                    */
/* ------------------------------------------------------------------ */
__global__ void demod_part() {
    __shared__ float ss[64];
    const int b   = blockIdx.x;
    const int co  = blockIdx.y * 128 + threadIdx.x;
    const int cis = blockIdx.z;
    const int c0  = cis * 64;
    if (threadIdx.x < 64) {
        float s = g_s[b * CIN + c0 + threadIdx.x];
        ss[threadIdx.x] = s * s;
    }
    __syncthreads();
    float a0 = 0.f, a1 = 0.f, a2 = 0.f, a3 = 0.f;
#pragma unroll
    for (int ci = 0; ci < 64; ci += 4) {
        a0 = fmaf(ss[ci + 0], g_wsq[(size_t)(c0 + ci + 0) * COUT + co], a0);
        a1 = fmaf(ss[ci + 1], g_wsq[(size_t)(c0 + ci + 1) * COUT + co], a1);
        a2 = fmaf(ss[ci + 2], g_wsq[(size_t)(c0 + ci + 2) * COUT + co], a2);
        a3 = fmaf(ss[ci + 3], g_wsq[(size_t)(c0 + ci + 3) * COUT + co], a3);
    }
    g_dp[(cis * NB + b) * COUT + co] = (a0 + a1) + (a2 + a3);
}

__global__ void demod_fin() {
    const int b  = blockIdx.x;
    const int co = threadIdx.x;
    float acc = 0.f;
#pragma unroll
    for (int cis = 0; cis < 8; cis++)
        acc += g_dp[(cis * NB + b) * COUT + co];
    g_d[b * COUT + co] = rsqrtf(acc * CONV_COEF * CONV_COEF + 1e-8f);
}

/* ------------------------------------------------------------------ */
/* fused: U = G (w*coef) G^T -> fp16 packed B-fragment order + wsq     */
/* ------------------------------------------------------------------ */
__global__ void uw_kernel(const float* __restrict__ w) {
    __shared__ uint32_t sU2[16][16][33];        /* 33792 B */
    const int ct = blockIdx.x >> 4, cc = blockIdx.x & 15;
    const int co_l = threadIdx.x & 31;
    const int ci_b = threadIdx.x >> 5;          /* 0..7 */
    const int ci0 = ct * 32, co0 = cc * 32;
    const int co = co0 + co_l;

#pragma unroll
    for (int jp = 0; jp < 2; jp++) {
        float Upair[2][16];
#pragma unroll
        for (int e = 0; e < 2; e++) {
            int ci = ci0 + ci_b * 4 + jp * 2 + e;
            float gm[3][3];
            float sq = 0.f;
#pragma unroll
            for (int tap = 0; tap < 9; tap++) {
                float v = w[(size_t)tap * CIN * COUT + (size_t)ci * COUT + co];
                sq = fmaf(v, v, sq);
                gm[tap / 3][tap % 3] = v * CONV_COEF;
            }
            g_wsq[(size_t)ci * COUT + co] = sq;
            float T[4][3];
#pragma unroll
            for (int c = 0; c < 3; c++) {
                T[0][c] = gm[0][c];
                T[1][c] = 0.5f * (gm[0][c] + gm[1][c] + gm[2][c]);
                T[2][c] = 0.5f * (gm[0][c] - gm[1][c] + gm[2][c]);
                T[3][c] = gm[2][c];
            }
#pragma unroll
            for (int r = 0; r < 4; r++) {
                Upair[e][r * 4 + 0] = T[r][0];
                Upair[e][r * 4 + 1] = 0.5f * (T[r][0] + T[r][1] + T[r][2]);
                Upair[e][r * 4 + 2] = 0.5f * (T[r][0] - T[r][1] + T[r][2]);
                Upair[e][r * 4 + 3] = T[r][2];
            }
        }
        int pair = ci_b * 2 + jp;
#pragma unroll
        for (int pos = 0; pos < 16; pos++)
            sU2[pos][pair][co_l] = h2u(__floats2half2_rn(Upair[0][pos], Upair[1][pos]));
    }
    __syncthreads();

    const int lane = threadIdx.x & 31;
    const int grp  = threadIdx.x >> 5;
    const int nblk = cc >> 2, wN = (cc >> 1) & 1;
    const int g = lane >> 2, tt = lane & 3;
#pragma unroll
    for (int i = 0; i < 8; i++) {
        int local = grp + 8 * i;
        int qs = local & 1, kg = (local >> 1) & 1, pos = local >> 2;
        int q = 2 * (cc & 1) + qs;
        int pr = kg * 8 + tt;
        int n_l = qs * 16 + g;
        uint4 o;
        o.x = sU2[pos][pr][n_l];
        o.y = sU2[pos][pr + 4][n_l];
        o.z = sU2[pos][pr][n_l + 8];
        o.w = sU2[pos][pr + 4][n_l + 8];
        size_t gidx = ((((size_t)(pos * 4 + nblk) * 16 + ct) * 2 + kg) * 2 + wN) * 4 + q;
        ((uint4*)g_U)[gidx * 32 + lane] = o;
    }
}

/* ------------------------------------------------------------------ */
/* V = B^T (x*s) B — 4 tile-rows per block (halo 1.33x)                */
/* block: (b, tq 8, h 2, ckg 16): tiles ty=4tq..4tq+3, tx=16h..16h+15  */
/* dyn smem: sx 10*34*32 f32 (43520B) | sbuf 16*2*256 half (16384B)    */
/* ------------------------------------------------------------------ */
#define VSX  (10 * 34 * 32 * 4)
#define VSM  (VSX + 16 * 2 * 256 * 2)

__global__ void v_kernel(const float* __restrict__ x) {
    extern __shared__ char vsm[];
    float*  sx   = (float*)vsm;
    __half* sbuf = (__half*)(vsm + VSX);
    int idx = blockIdx.x;
    const int ckg = idx & 15;  idx >>= 4;
    const int h   = idx & 1;   idx >>= 1;
    const int tq  = idx & 7;
    const int b   = idx >> 3;
    const int tid = threadIdx.x;

    /* stage x: rows 8tq-1..8tq+8 (10), cols 32h-1..32h+32 (34), 32 ch */
    const uint32_t sxa = su32(sx);
    {
        const int iyb = 8 * tq - 1, ixb = 32 * h - 1;
#pragma unroll
        for (int j = 0; j < 11; j++) {
            int i = tid + j * 256;
            if (i < 2720) {                     /* 340 (row,col) x 8 cp16 */
                int q  = i & 7;
                int rc = i >> 3;
                int row = rc / 34, col = rc - 34 * row;
                int iy = iyb + row, ix = ixb + col;
                uint32_t dst = sxa + (rc * 32 + q * 4) * 4;
                if ((unsigned)iy < HW && (unsigned)ix < HW) {
                    cp16(dst, x + ((size_t)((b * HW + iy) * HW + ix)) * CIN + ckg * 32 + q * 4);
                } else {
                    *(float4*)((char*)sx + (rc * 32 + q * 4) * 4) = make_float4(0.f, 0.f, 0.f, 0.f);
                }
            }
        }
    }
    cp_commit();
    cp_wait<0>();
    __syncthreads();

#pragma unroll
    for (int p = 0; p < 4; p++) {               /* tile-row pass */
        if (p) __syncthreads();                 /* sbuf reuse guard */
#pragma unroll
        for (int u = 0; u < 2; u++) {
            int uid = tid + 256 * u;
            int tl = uid >> 5, ch = uid & 31;
            float s = g_s[b * 512 + ckg * 32 + ch];
            float d[4][4];
#pragma unroll
            for (int r = 0; r < 4; r++)
#pragma unroll
                for (int c = 0; c < 4; c++)
                    d[r][c] = sx[((2 * p + r) * 34 + 2 * tl + c) * 32 + ch] * s;
            float tt[4][4];
#pragma unroll
            for (int c = 0; c < 4; c++) {
                tt[0][c] = d[0][c] - d[2][c];
                tt[1][c] = d[1][c] + d[2][c];
                tt[2][c] = d[2][c] - d[1][c];
                tt[3][c] = d[1][c] - d[3][c];
            }
            int g = tl & 7, hh = tl >> 3;
            int kg = ch >> 4, kk = ch & 15, j = kk >> 1;
            int off = g * 64 + (j & 3) * 16 + (j >> 2) * 8 + hh * 4 + (kk & 1) * 2;
#pragma unroll
            for (int i = 0; i < 4; i++) {
                float v0 = tt[i][0] - tt[i][2];
                float v1 = tt[i][1] + tt[i][2];
                float v2 = tt[i][2] - tt[i][1];
                float v3 = tt[i][1] - tt[i][3];
                char* pl = (char*)sbuf + kg * 512;
                *(__half*)(pl + (i * 4 + 0) * 1024 + off) = __float2half(v0);
                *(__half*)(pl + (i * 4 + 1) * 1024 + off) = __float2half(v1);
                *(__half*)(pl + (i * 4 + 2) * 1024 + off) = __float2half(v2);
                *(__half*)(pl + (i * 4 + 3) * 1024 + off) = __float2half(v3);
            }
        }
        __syncthreads();
        const int mblk = b * 64 + (4 * tq + p) * 2 + h;
#pragma unroll
        for (int j = 0; j < 4; j++) {
            int cidx = tid + 256 * j;
            int plane = cidx >> 5, o16 = (cidx & 31) * 16;
            int pos = plane >> 1, kg = plane & 1;
            char* dst = (char*)g_V + (((size_t)(pos * 32 + ckg * 2 + kg)) * 1024 + mblk) * 512 + o16;
            *(uint4*)dst = *(uint4*)((char*)sbuf + plane * 512 + o16);
        }
    }
}

/* ------------------------------------------------------------------ */
/* GEMM per pos: M = V U ; CTA 128x128, warp 64x32, K-chunk 64         */
/* ------------------------------------------------------------------ */
#define GSTG 32768

__device__ __forceinline__ void g_load(uint32_t sb, const char* Vsrc, const char* Usrc,
                                       int s, int tid) {
#pragma unroll
    for (int j = 0; j < 8; j++) {
        int i = tid + 256 * j;
        if (i < 1024) {
            int kg = i >> 8, mo = i & 255;
            const char* src = Vsrc + ((size_t)(s * 4 + kg) * 1024 + (mo >> 5)) * 512 + (mo & 31) * 16;
            cp16(sb + kg * 4096 + mo * 16, src);
        } else {
            int i2 = i - 1024;
            cp16(sb + 16384 + i2 * 16, Usrc + (size_t)s * 16384 + i2 * 16);
        }
    }
}

__global__ __launch_bounds__(256, 2)
void gemm_kernel() {
    extern __shared__ char sm[];
    const int tid  = threadIdx.x;
    const int warp = tid >> 5;
    const int lane = tid & 31;
    const int g = lane >> 2, t = lane & 3;
    const int wn = warp & 3, wm = warp >> 2;
    const int nblk = blockIdx.x;
    const int mby  = blockIdx.y;
    const int pos  = blockIdx.z;

    const char* Vsrc = (const char*)g_V + ((size_t)pos * 32 * 1024 + (size_t)mby * 8) * 512;
    const char* Usrc = (const char*)g_U + (size_t)((pos * 4 + nblk) * 16) * 8192;
    const uint32_t sb = su32(sm);

    float acc[4][4][4];
#pragma unroll
    for (int mi = 0; mi < 4; mi++)
#pragma unroll
        for (int ni = 0; ni < 4; ni++)
#pragma unroll
            for (int r = 0; r < 4; r++) acc[mi][ni][r] = 0.f;

    g_load(sb, Vsrc, Usrc, 0, tid); cp_commit();
    g_load(sb + GSTG, Vsrc, Usrc, 1, tid); cp_commit();

    for (int s = 0; s < 8; s++) {
        cp_wait<1>();
        __syncthreads();
        const int s2 = s + 2;
        if (s2 < 8)
            g_load(sb + (s2 % 3) * GSTG, Vsrc, Usrc, s2, tid);
        cp_commit();

        const char* st = sm + (s % 3) * GSTG;
#pragma unroll
        for (int j = 0; j < 4; j++) {
            const char* ab = st + j * 4096 + wm * 2048 + g * 64 + t * 16;
            float4 Af[4];
#pragma unroll
            for (int mi = 0; mi < 4; mi++)
                Af[mi] = *(const float4*)(ab + mi * 512);
            const char* bb = st + 16384 + (j >> 1) * 8192 + (j & 1) * 4096
                           + (wn >> 1) * 2048 + (wn & 1) * 1024 + lane * 16;
            float4 Bf[2];
            Bf[0] = *(const float4*)bb;
            Bf[1] = *(const float4*)(bb + 512);
#pragma unroll
            for (int mi = 0; mi < 4; mi++)
#pragma unroll
                for (int ni = 0; ni < 4; ni++) {
                    const float4& B = Bf[ni >> 1];
                    uint32_t b0 = __float_as_uint((ni & 1) ? B.z : B.x);
                    uint32_t b1 = __float_as_uint((ni & 1) ? B.w : B.y);
                    mma16(acc[mi][ni],
                          __float_as_uint(Af[mi].x), __float_as_uint(Af[mi].y),
                          __float_as_uint(Af[mi].z), __float_as_uint(Af[mi].w),
                          b0, b1);
                }
        }
    }

    __half* Mp = g_M + (size_t)pos * NTILE * 512;
    const int m0 = mby * 128 + wm * 64;
    const int c0 = nblk * 128 + wn * 32;
#pragma unroll
    for (int mi = 0; mi < 4; mi++) {
        int r0 = m0 + mi * 16 + g;
#pragma unroll
        for (int ni = 0; ni < 4; ni++) {
            int cc = c0 + (ni >> 1) * 16 + (ni & 1) * 8 + t * 2;
            *(uint32_t*)(Mp + (size_t)r0 * 512 + cc) =
                h2u(__floats2half2_rn(acc[mi][ni][0], acc[mi][ni][1]));
            *(uint32_t*)(Mp + (size_t)(r0 + 8) * 512 + cc) =
                h2u(__floats2half2_rn(acc[mi][ni][2], acc[mi][ni][3]));
        }
    }
}

/* ------------------------------------------------------------------ */
/* inverse transform: y = A^T M A, * demod + bias — 2 co per thread    */
/* ------------------------------------------------------------------ */
__device__ __forceinline__ float2 f2add(float2 a, float2 b) {
    return make_float2(a.x + b.x, a.y + b.y);
}
__device__ __forceinline__ float2 f2sub(float2 a, float2 b) {
    return make_float2(a.x - b.x, a.y - b.y);
}

__global__ void inv_kernel(const float* __restrict__ bias, float* __restrict__ out) {
    int Wu = blockIdx.x * 16 + (threadIdx.x >> 5);
    int lane = threadIdx.x & 31;
    int tile = Wu >> 3, cog = Wu & 7;
    int co = cog * 64 + lane * 2;
    int b = tile >> 10, tl = tile & 1023, ty = tl >> 5, tx = tl & 31;

    float2 M[16];
#pragma unroll
    for (int pos = 0; pos < 16; pos++) {
        __half2 hv = *(const __half2*)(g_M + ((size_t)pos * NTILE + tile) * 512 + co);
        M[pos] = __half22float2(hv);
    }

    float2 P0[4], P1[4];
#pragma unroll
    for (int r = 0; r < 4; r++) {
        P0[r] = f2add(f2add(M[r * 4 + 0], M[r * 4 + 1]), M[r * 4 + 2]);
        P1[r] = f2sub(f2sub(M[r * 4 + 1], M[r * 4 + 2]), M[r * 4 + 3]);
    }
    float2 y00 = f2add(f2add(P0[0], P0[1]), P0[2]);
    float2 y10 = f2sub(f2sub(P0[1], P0[2]), P0[3]);
    float2 y01 = f2add(f2add(P1[0], P1[1]), P1[2]);
    float2 y11 = f2sub(f2sub(P1[1], P1[2]), P1[3]);

    float d0 = g_d[b * 512 + co],  d1 = g_d[b * 512 + co + 1];
    float b0 = bias[co],           b1 = bias[co + 1];
    int Y = 2 * ty, X = 2 * tx;
    float* o = out + ((size_t)((b * HW + Y) * HW + X)) * 512 + co;
    *(float2*)(o)                  = make_float2(y00.x * d0 + b0, y00.y * d1 + b1);
    *(float2*)(o + 512)            = make_float2(y01.x * d0 + b0, y01.y * d1 + b1);
    *(float2*)(o + HW * 512)       = make_float2(y10.x * d0 + b0, y10.y * d1 + b1);
    *(float2*)(o + HW * 512 + 512) = make_float2(y11.x * d0 + b0, y11.y * d1 + b1);
}

/* ------------------------------------------------------------------ */
extern "C" void kernel_launch(void* const* d_in, const int* in_sizes, int n_in,
                              void* d_out, int out_size) {
    (void)in_sizes; (void)n_in; (void)out_size;
    const float* x    = (const float*)d_in[0];
    const float* wl   = (const float*)d_in[1];
    const float* w    = (const float*)d_in[2];
    const float* bias = (const float*)d_in[3];
    const float* fcw  = (const float*)d_in[4];
    const float* fcb  = (const float*)d_in[5];
    float* out = (float*)d_out;

    uw_kernel<<<256, 256>>>(w);            /* fused U-pack + wsq */
    style_part<<<dim3(NB, 4, 8), 128>>>(wl, fcw);
    style_fin<<<NB, CIN>>>(fcb);
    demod_part<<<dim3(NB, 4, 8), 128>>>();
    demod_fin<<<NB, COUT>>>();

    cudaFuncSetAttribute(v_kernel, cudaFuncAttributeMaxDynamicSharedMemorySize, VSM);
    v_kernel<<<4096, 256, VSM>>>(x);       /* 16b x 8tq x 2h x 16ckg */

    cudaFuncSetAttribute(gemm_kernel, cudaFuncAttributeMaxDynamicSharedMemorySize, 3 * GSTG);
    gemm_kernel<<<dim3(4, 128, 16), 256, 3 * GSTG>>>();

    inv_kernel<<<8192, 512>>>(bias, out);
}